// round 4
// baseline (speedup 1.0000x reference)
#include <cuda_runtime.h>
#include <math.h>

#define BB 4
#define TT 16
#define NN 512
#define FF 5
#define HH 64
#define RR 824
#define SS (BB*NN)            // 2048
#define RB 16
#define LSTM_BLOCKS (SS/RB)   // 128
#define RELW_BLOCKS 1024      // 4096 warps, 64 pairs each

// ---------------- device scratch ----------------
__device__ float g_hf[SS*HH];
__device__ float g_out[SS*HH];
__device__ float g_tail[SS];
__device__ float g_relw[NN*NN];
__device__ short g_idx[NN*NN];   // per-n compressed active-m lists
__device__ int   g_cnt[NN];

typedef unsigned long long ull;

__device__ __forceinline__ void ffma2_(ull& d, ull a, ull b){
    asm("fma.rn.f32x2 %0, %1, %2, %0;" : "+l"(d) : "l"(a), "l"(b));
}
__device__ __forceinline__ float2 unpack2_(ull v){
    float2 r; asm("mov.b64 {%0, %1}, %2;" : "=f"(r.x), "=f"(r.y) : "l"(v)); return r;
}
__device__ __forceinline__ ull pack2_(float lo, float hi){
    ull r; asm("mov.b64 %0, {%1, %2};" : "=l"(r) : "f"(lo), "f"(hi)); return r;
}
__device__ __forceinline__ float sigmoidf_(float v){
    return __fdividef(1.0f, 1.0f + __expf(-v));
}
__device__ __forceinline__ float tanh_fast_(float v){
    // tanh(x) = 1 - 2/(1+exp(2x)); exact at both saturations, ~1e-7 rel err
    float e = __expf(2.0f * v);
    return 1.0f - __fdividef(2.0f, 1.0f + e);
}
__device__ __forceinline__ float leaky_(float v){ return v >= 0.0f ? v : 0.01f*v; }

// =====================================================================
// K_FUSED: blocks [0,128): forward LSTM (FMA-bound, f32x2 packed).
//          blocks [128, 128+1024): sparse rel_weight dots (HBM-bound).
// The two populations co-reside (74KB smem -> 3 blocks/SM) so the HBM
// stream hides under the LSTM's FMA pipe.
// =====================================================================
__global__ __launch_bounds__(128) void k_fused(
    const float* __restrict__ x,
    const float* __restrict__ Wih, const float* __restrict__ Whh,
    const float* __restrict__ bih, const float* __restrict__ bhh,
    const float* __restrict__ rel_enc, const float* __restrict__ rel_mask,
    const float* __restrict__ fc1_w, const float* __restrict__ fc1_b)
{
    if (blockIdx.x >= LSTM_BLOCKS) {
        // ---------------- relw: one warp scans 64 pairs, dots only active ones
        const int w    = (blockIdx.x - LSTM_BLOCKS)*4 + (threadIdx.x >> 5);
        const int lane = threadIdx.x & 31;
        const int base = w * 64;
        const float b0 = __ldg(&fc1_b[0]);
        const float4* w4 = (const float4*)fc1_w;
        unsigned act0 = __ballot_sync(0xffffffffu, __ldg(&rel_mask[base + lane])      > -1.0f);
        unsigned act1 = __ballot_sync(0xffffffffu, __ldg(&rel_mask[base + 32 + lane]) > -1.0f);
        #pragma unroll 1
        for (int half = 0; half < 2; ++half) {
            unsigned act = half ? act1 : act0;
            const int hb = base + half*32;
            while (act) {
                const int j = __ffs(act) - 1; act &= act - 1u;
                const int pair = hb + j;
                const float4* e4 = (const float4*)(rel_enc + (size_t)pair * RR);
                float dot = 0.f;
                #pragma unroll
                for (int it = 0; it < 7; ++it) {
                    const int i = it*32 + lane;
                    if (i < RR/4) {
                        const float4 e = e4[i];
                        const float4 wv = __ldg(&w4[i]);
                        dot += e.x*wv.x + e.y*wv.y + e.z*wv.z + e.w*wv.w;
                    }
                }
                #pragma unroll
                for (int off = 16; off > 0; off >>= 1)
                    dot += __shfl_down_sync(0xffffffffu, dot, off);
                if (lane == 0) g_relw[pair] = leaky_(dot + b0);
            }
        }
        return;
    }

    // ---------------- LSTM ----------------
    extern __shared__ float sm[];
    float*  sWhhT = sm;                       // [64][256]  transposed Whh
    float2* hsh2  = (float2*)(sm + 64*256);   // [16 rows][64 k], each {h,h}
    float2* xsh2  = hsh2 + RB*64;             // [16 rows][5 f],  each {x,x}

    const int tid = threadIdx.x;
    const int tg  = tid & 31;                 // hidden-pair index
    const int tr  = tid >> 5;                 // row group 0..3
    const int s0  = blockIdx.x * RB;
    const int b   = s0 >> 9;
    const int n0  = s0 & 511;
    const int j0  = 2*tg;                     // unit pair base within a gate block

    // stage Whh transposed into smem
    for (int j = tid; j < 256; j += 128) {
        const float4* src = (const float4*)(Whh + j*64);
        #pragma unroll
        for (int kq = 0; kq < 16; ++kq) {
            const float4 v = src[kq];
            const int k = kq*4;
            sWhhT[(k+0)*256 + j] = v.x;
            sWhhT[(k+1)*256 + j] = v.y;
            sWhhT[(k+2)*256 + j] = v.z;
            sWhhT[(k+3)*256 + j] = v.w;
        }
    }
    // per-thread constant gate weights in registers (packed pairs)
    ull bias2[4], wih2[FF][4];
    #pragma unroll
    for (int g = 0; g < 4; ++g) {
        const int j = g*64 + j0;
        bias2[g] = pack2_(bih[j] + bhh[j], bih[j+1] + bhh[j+1]);
        #pragma unroll
        for (int f = 0; f < FF; ++f)
            wih2[f][g] = pack2_(Wih[j*FF + f], Wih[(j+1)*FF + f]);
    }
    for (int i = tid; i < RB*64; i += 128) hsh2[i] = make_float2(0.f, 0.f);
    __syncthreads();

    float c[4][2];
    float2 hout[4];
    #pragma unroll
    for (int rr = 0; rr < 4; ++rr) {
        c[rr][0] = 0.f; c[rr][1] = 0.f;
        hout[rr] = make_float2(0.f, 0.f);
    }

    const float* xbase = x + ((size_t)b*TT*NN + n0)*FF;

    for (int t = 0; t < TT; ++t) {
        if (tid < RB*FF) {
            const float v = xbase[(size_t)t*NN*FF + tid];  // 80 contiguous floats
            xsh2[tid] = make_float2(v, v);
        }
        __syncthreads();   // xsh2 ready; hsh2(t-1) stores visible

        ull acc[4][4];
        #pragma unroll
        for (int rr = 0; rr < 4; ++rr) {
            #pragma unroll
            for (int g = 0; g < 4; ++g) acc[rr][g] = bias2[g];
            const ull* xp = (const ull*)(xsh2 + (tr*4 + rr)*FF);
            #pragma unroll
            for (int f = 0; f < FF; ++f) {
                const ull x2 = xp[f];
                #pragma unroll
                for (int g = 0; g < 4; ++g) ffma2_(acc[rr][g], wih2[f][g], x2);
            }
        }

        const ull* hrow0 = (const ull*)(hsh2 + (tr*4)*64);
        #pragma unroll 2
        for (int kk = 0; kk < 64; ++kk) {
            const ull* wr = (const ull*)(sWhhT + kk*256) + tg;
            const ull w0 = wr[0], w1 = wr[32], w2 = wr[64], w3 = wr[96];
            #pragma unroll
            for (int rr = 0; rr < 4; ++rr) {
                const ull hv = hrow0[rr*64 + kk];       // broadcast {h,h}
                ffma2_(acc[rr][0], w0, hv);
                ffma2_(acc[rr][1], w1, hv);
                ffma2_(acc[rr][2], w2, hv);
                ffma2_(acc[rr][3], w3, hv);
            }
        }

        #pragma unroll
        for (int rr = 0; rr < 4; ++rr) {
            const float2 gi = unpack2_(acc[rr][0]);
            const float2 gf = unpack2_(acc[rr][1]);
            const float2 gg = unpack2_(acc[rr][2]);
            const float2 go = unpack2_(acc[rr][3]);
            const float i0 = sigmoidf_(gi.x), i1 = sigmoidf_(gi.y);
            const float f0 = sigmoidf_(gf.x), f1 = sigmoidf_(gf.y);
            const float g0 = tanh_fast_(gg.x), g1 = tanh_fast_(gg.y);
            const float o0 = sigmoidf_(go.x), o1 = sigmoidf_(go.y);
            c[rr][0] = f0*c[rr][0] + i0*g0;
            c[rr][1] = f1*c[rr][1] + i1*g1;
            hout[rr].x = o0 * tanh_fast_(c[rr][0]);
            hout[rr].y = o1 * tanh_fast_(c[rr][1]);
        }
        __syncthreads();   // all hsh2 reads of this step done
        #pragma unroll
        for (int rr = 0; rr < 4; ++rr) {
            float2* hp = hsh2 + (tr*4 + rr)*64;
            hp[j0]   = make_float2(hout[rr].x, hout[rr].x);
            hp[j0+1] = make_float2(hout[rr].y, hout[rr].y);
        }
    }

    #pragma unroll
    for (int rr = 0; rr < 4; ++rr)
        *(float2*)&g_hf[(size_t)(s0 + tr*4 + rr)*64 + j0] = hout[rr];
}

// =====================================================================
// K_COMPRESS: one warp per n builds the ordered list of active m.
// =====================================================================
__global__ __launch_bounds__(256) void k_compress(const float* __restrict__ rel_mask)
{
    const int n    = (blockIdx.x * blockDim.x + threadIdx.x) >> 5;
    const int lane = threadIdx.x & 31;
    if (n >= NN) return;
    int cnt = 0;
    #pragma unroll
    for (int it = 0; it < 16; ++it) {
        const int m = it*32 + lane;
        const bool act = rel_mask[n*NN + m] > -1.0f;
        const unsigned bal = __ballot_sync(0xffffffffu, act);
        if (act) g_idx[n*NN + cnt + __popc(bal & ((1u << lane) - 1u))] = (short)m;
        cnt += __popc(bal);
    }
    if (lane == 0) g_cnt[n] = cnt;
}

// =====================================================================
// K_POST: backward LSTM single step (hs_b[0]) + fc0 + tail. head cancels.
// =====================================================================
__global__ __launch_bounds__(64) void k_post(
    const float* __restrict__ x,
    const float* __restrict__ Wih_b,
    const float* __restrict__ bih_b, const float* __restrict__ bhh_b,
    const float* __restrict__ fc0_w, const float* __restrict__ fc0_b,
    const float* __restrict__ fc3_w, const float* __restrict__ fc3_b)
{
    __shared__ __align__(16) float lastsh[128];
    __shared__ float red[2];
    const int s = blockIdx.x;
    const int b = s >> 9, n = s & 511;
    const int k = threadIdx.x;

    const float* xp = x + (((b*TT + (TT-1))*NN) + n)*FF;
    const float x0 = xp[0], x1 = xp[1], x2 = xp[2], x3 = xp[3], x4 = xp[4];

    auto gate = [&](int j) {
        const float* w = Wih_b + j*FF;
        return bih_b[j] + bhh_b[j] + x0*w[0] + x1*w[1] + x2*w[2] + x3*w[3] + x4*w[4];
    };
    const float iv = sigmoidf_(gate(k));
    const float gv = tanh_fast_(gate(128 + k));
    const float ov = sigmoidf_(gate(192 + k));
    const float hb = ov * tanh_fast_(iv * gv);

    lastsh[64 + k] = hb;
    lastsh[k] = g_hf[(size_t)s*64 + k];
    __syncthreads();

    float a = fc0_b[k];
    const float4* wv = (const float4*)(fc0_w + k*128);
    const float4* lv = (const float4*)lastsh;
    #pragma unroll
    for (int q = 0; q < 32; ++q) {
        const float4 w = wv[q], l = lv[q];
        a += w.x*l.x + w.y*l.y + w.z*l.z + w.w*l.w;
    }
    const float outv = leaky_(a);
    g_out[(size_t)s*64 + k] = outv;

    float v = outv * fc3_w[k];
    #pragma unroll
    for (int off = 16; off > 0; off >>= 1) v += __shfl_down_sync(0xffffffffu, v, off);
    if ((k & 31) == 0) red[k >> 5] = v;
    __syncthreads();
    if (k == 0) g_tail[s] = leaky_(red[0] + red[1] + fc3_b[0]);
}

// =====================================================================
// K4: one warp per (b,n). Sparse masked softmax + aggregation + prediction.
// No block barriers; iterates only the ~10% active m via g_idx.
// =====================================================================
__global__ __launch_bounds__(256) void k4(
    const float* __restrict__ pred_w, const float* __restrict__ pred_b,
    float* __restrict__ outp)
{
    const int gw   = (blockIdx.x * blockDim.x + threadIdx.x) >> 5;  // (b,n) id
    const int lane = threadIdx.x & 31;
    const int b = gw >> 9, n = gw & 511;
    const int cnt = g_cnt[n];
    const short* idx  = g_idx  + n*NN;
    const float* tail = g_tail + b*NN;
    const float* rwn  = g_relw + n*NN;

    // pass 1: max over active logits (head term is constant per row -> cancels)
    float mx = -1e30f;
    for (int i = lane; i < cnt; i += 32) {
        const int m = idx[i];
        mx = fmaxf(mx, tail[m] + rwn[m]);
    }
    #pragma unroll
    for (int off = 16; off > 0; off >>= 1)
        mx = fmaxf(mx, __shfl_xor_sync(0xffffffffu, mx, off));

    // pass 2: fused exp + weighted aggregation (all lanes walk the same m)
    const float* outb = g_out + (size_t)b * NN * 64;
    float sum = 0.f, a0 = 0.f, a1 = 0.f;
    #pragma unroll 1
    for (int i = 0; i < cnt; ++i) {
        const int m = idx[i];                       // broadcast
        const float e = __expf(tail[m] + rwn[m] - mx);
        sum += e;
        a0 += e * outb[m*64 + lane];
        a1 += e * outb[m*64 + 32 + lane];
    }
    const float inv = __fdividef(1.0f, sum);
    const float pr0 = a0 * inv, pr1 = a1 * inv;
    const float o0 = outb[n*64 + lane], o1 = outb[n*64 + 32 + lane];

    float v = pred_w[lane]*o0 + pred_w[32 + lane]*o1
            + pred_w[64 + lane]*pr0 + pred_w[96 + lane]*pr1;
    #pragma unroll
    for (int off = 16; off > 0; off >>= 1)
        v += __shfl_down_sync(0xffffffffu, v, off);
    if (lane == 0) outp[gw] = leaky_(v + pred_b[0]);
}

// =====================================================================
extern "C" void kernel_launch(void* const* d_in, const int* in_sizes, int n_in,
                              void* d_out, int out_size)
{
    const float* x        = (const float*)d_in[0];
    const float* rel_enc  = (const float*)d_in[1];
    const float* rel_mask = (const float*)d_in[2];
    const float* Wih_f    = (const float*)d_in[3];
    const float* Whh_f    = (const float*)d_in[4];
    const float* bih_f    = (const float*)d_in[5];
    const float* bhh_f    = (const float*)d_in[6];
    const float* Wih_b    = (const float*)d_in[7];
    // d_in[8] = Whh_b unused (backward contributes only its first step)
    const float* bih_b    = (const float*)d_in[9];
    const float* bhh_b    = (const float*)d_in[10];
    const float* fc0_w    = (const float*)d_in[11];
    const float* fc0_b    = (const float*)d_in[12];
    const float* fc1_w    = (const float*)d_in[13];
    const float* fc1_b    = (const float*)d_in[14];
    // d_in[15..16] = fc2 (head) — cancels inside softmax
    const float* fc3_w    = (const float*)d_in[17];
    const float* fc3_b    = (const float*)d_in[18];
    const float* pred_w   = (const float*)d_in[19];
    const float* pred_b   = (const float*)d_in[20];
    // d_in[21] = all_one unused

    const int smem = (64*256 + RB*64*2 + RB*FF*2) * (int)sizeof(float);  // 74368 B
    cudaFuncSetAttribute(k_fused, cudaFuncAttributeMaxDynamicSharedMemorySize, smem);

    k_fused<<<LSTM_BLOCKS + RELW_BLOCKS, 128, smem>>>(
        x, Wih_f, Whh_f, bih_f, bhh_f, rel_enc, rel_mask, fc1_w, fc1_b);
    k_compress<<<NN/8, 256>>>(rel_mask);
    k_post<<<SS, 64>>>(x, Wih_b, bih_b, bhh_b, fc0_w, fc0_b, fc3_w, fc3_b);
    k4<<<SS/8, 256>>>(pred_w, pred_b, (float*)d_out);
}